// round 16
// baseline (speedup 1.0000x reference)
#include <cuda_runtime.h>

// ---------------------------------------------------------------------------
// Problem constants
// ---------------------------------------------------------------------------
#define Bc    8
#define Ac    60000
#define Cc    150                 // 1 + (10+19+39+69+12)
#define Gc    20
#define Tc    5
#define BAc   (Bc * Ac)           // 480,000 anchors
#define NCONF (BAc * Cc)          // 72,000,000 floats
#define NV16  (NCONF / 16)        // 4,500,000 16-channel groups
#define RW    8                   // padded words per bitmask row
#define NROWS (Bc * (Gc + 1))     // 168 rows
#define NBLK  592                 // 148 SMs * 4 blocks: single wave @ 64 regs

#define POSBIT 0x40000000u
#define HL2    0.34657359027997264f   // 0.5 * ln(2)

__device__ unsigned g_bits[NROWS * RW];
__device__ int      g_row[BAc];    // per-anchor: row | pos<<30 | neg->sign bit
__device__ double   g_acc[3];      // [0]=reg_sum, [1]=cls_sum, [2]=num_pos
__device__ unsigned g_done;        // completed-block ticket counter

// ---------------------------------------------------------------------------
// MUFU wrappers
// ---------------------------------------------------------------------------
__device__ __forceinline__ float mufu_tanh(float x) {
    float y; asm("tanh.approx.f32 %0, %1;" : "=f"(y) : "f"(x)); return y;
}
__device__ __forceinline__ float mufu_lg2(float x) {
    float y; asm("lg2.approx.f32 %0, %1;" : "=f"(y) : "f"(x)); return y;
}

// ---------------------------------------------------------------------------
// Focal, branch/predicate-free (R15-proven):
//   sgn = label ? +0.5 : -0.5   (bit -> sign word, pure ALU)
//   t = tanh(x/2); P = 0.5 + sgn*t; w = 0.5 - sgn*t
//   coef = cp*(sgn-1), cp = mask*0.5*ln2  ->  -A*ln2*mask exactly
//   acc += coef * lg2(P) * w^2
// ---------------------------------------------------------------------------
__device__ __forceinline__ void focal(float x, unsigned nb, int k, float cp,
                                      float& acc) {
    unsigned sgnw = ((nb << (31 - k)) & 0x80000000u) | 0x3F000000u;
    float sgn  = __uint_as_float(sgnw);
    float t    = mufu_tanh(0.5f * x);
    float P    = fmaf(sgn, t, 0.5f);
    float w    = fmaf(-sgn, t, 0.5f);
    float lgP  = mufu_lg2(P);
    float coef = cp * (sgn - 1.0f);
    acc = fmaf(coef * lgP, w * w, acc);
}

// ---------------------------------------------------------------------------
// Kernel 1 (prep): per-anchor routing word + label bitmask table.
// ---------------------------------------------------------------------------
__global__ void prep_kernel(const int* __restrict__ lbin,
                            const int* __restrict__ gt_labels) {
    int a = blockIdx.x * 256 + threadIdx.x;
    if (a < BAc) {
        int lb = lbin[a];
        int b  = a / Ac;
        unsigned enc = (unsigned)(b * (Gc + 1) + max(lb, 0));
        if (lb > 0) enc |= POSBIT;
        if (lb < 0) enc |= 0x80000000u;
        g_row[a] = (int)enc;
    }
    if (blockIdx.x == 0 && threadIdx.x < NROWS) {
        int b = threadIdx.x / (Gc + 1), g = threadIdx.x % (Gc + 1);
        unsigned w[RW] = {0u, 0u, 0u, 0u, 0u, 0u, 0u, 0u};
        if (g > 0) {
            w[0] = 1u;
            const int off[5] = {1, 11, 30, 69, 138};
            int grp = g - 1;
#pragma unroll
            for (int h = 0; h < 5; h++)
#pragma unroll
                for (int t = 0; t < Tc; t++) {
                    int v = __ldg(&gt_labels[((b * Gc + grp) * 5 + h) * Tc + t]);
                    if (v >= 0) {
                        int bit = off[h] + v;
                        w[bit >> 5] |= (1u << (bit & 31));
                    }
                }
        }
#pragma unroll
        for (int k = 0; k < RW; k++)
            g_bits[threadIdx.x * RW + k] = w[k];
    }
}

// ---------------------------------------------------------------------------
// Kernel 2 (main): 16 channels per iteration, next iteration prefetched.
// ---------------------------------------------------------------------------
__global__ void __launch_bounds__(256, 4)
main_kernel(const float4* __restrict__ conf4,
            const float4* __restrict__ pred4,
            const float4* __restrict__ gt4,
            float*        __restrict__ out) {
    __shared__ unsigned sb[NROWS * RW];        // 5.25 KB
    for (int i = threadIdx.x; i < NROWS * RW; i += 256)
        sb[i] = g_bits[i];
    __syncthreads();

    const int tid    = blockIdx.x * 256 + threadIdx.x;
    const int stride = NBLK * 256;

    float cls0 = 0.f, cls1 = 0.f, cls2 = 0.f, cls3 = 0.f;

    // ---- classification with 1-deep software pipeline (8 LDG in flight) ----
    // tid < NV16 always (189,440 threads << 4.5M groups)
    float4 n0 = __ldcs(&conf4[4 * tid]);
    float4 n1 = __ldcs(&conf4[4 * tid + 1]);
    float4 n2 = __ldcs(&conf4[4 * tid + 2]);
    float4 n3 = __ldcs(&conf4[4 * tid + 3]);

    for (int j = tid; j < NV16; ) {
        float4 v0 = n0, v1 = n1, v2 = n2, v3 = n3;
        int jc = j;
        j += stride;
        if (j < NV16) {                        // prefetch next group
            n0 = __ldcs(&conf4[4 * j]);
            n1 = __ldcs(&conf4[4 * j + 1]);
            n2 = __ldcs(&conf4[4 * j + 2]);
            n3 = __ldcs(&conf4[4 * j + 3]);
        }

        unsigned base = (unsigned)jc << 4;         // 16 channels per group
        unsigned a = base / (unsigned)Cc;          // magic-mul
        int c = (int)(base - a * Cc);              // even, 0..148
        int rv = __ldg(&g_row[a]);
        int row = rv & 0xFFFF;

        const unsigned* rp = &sb[(row << 3) + (c >> 5)];
        unsigned bits = __funnelshift_r(rp[0], rp[1], c);  // low 16 = labels
        float cm = (rv >= 0) ? HL2 : 0.f;          // cp = mask * 0.5*ln2
        float cp0 = cm, cp1 = cm, cp2 = cm, cp3 = cm;
        float cp4 = cm, cp5 = cm, cp6 = cm, cp7 = cm;

        if (c >= 136) {                            // anchor crossing (~9%)
            int n1c = Cc - c;                      // 2..14 lanes in anchor a
            int rv2 = __ldg(&g_row[a + 1]);
            int row2 = rv2 & 0xFFFF;
            unsigned bits2 = sb[row2 << 3];
            bits = (bits & ((1u << n1c) - 1u)) | (bits2 << n1c);
            float cm2 = (rv2 >= 0) ? HL2 : 0.f;
            if (n1c <=  2) cp1 = cm2;
            if (n1c <=  4) cp2 = cm2;
            if (n1c <=  6) cp3 = cm2;
            if (n1c <=  8) cp4 = cm2;
            if (n1c <= 10) cp5 = cm2;
            if (n1c <= 12) cp6 = cm2;
            cp7 = cm2;
        }

        unsigned nb = ~bits;

        focal(v0.x, nb,  0, cp0, cls0);
        focal(v0.y, nb,  1, cp0, cls1);
        focal(v0.z, nb,  2, cp1, cls2);
        focal(v0.w, nb,  3, cp1, cls3);
        focal(v1.x, nb,  4, cp2, cls0);
        focal(v1.y, nb,  5, cp2, cls1);
        focal(v1.z, nb,  6, cp3, cls2);
        focal(v1.w, nb,  7, cp3, cls3);
        focal(v2.x, nb,  8, cp4, cls0);
        focal(v2.y, nb,  9, cp4, cls1);
        focal(v2.z, nb, 10, cp5, cls2);
        focal(v2.w, nb, 11, cp5, cls3);
        focal(v3.x, nb, 12, cp6, cls0);
        focal(v3.y, nb, 13, cp6, cls1);
        focal(v3.z, nb, 14, cp7, cls2);
        focal(v3.w, nb, 15, cp7, cls3);
    }

    // ---- regression + pos count over 480k anchors ----
    float reg = 0.f, npos = 0.f;
    for (int a1 = tid; a1 < BAc; a1 += stride) {
        int rv = __ldg(&g_row[a1]);
        if (rv & (int)POSBIT) {
            npos += 1.0f;
            float4 p = pred4[a1];
            float4 g = gt4[a1];
            float d[4] = {p.x - g.x, p.y - g.y, p.z - g.z, p.w - g.w};
#pragma unroll
            for (int k = 0; k < 4; k++) {
                float n = fabsf(d[k]);
                reg += (n < (1.0f / 9.0f)) ? 4.5f * n * n : n - (1.0f / 18.0f);
            }
        }
    }

    // ---- block reduction ----
    float cls = (cls0 + cls1) + (cls2 + cls3);
#pragma unroll
    for (int o = 16; o > 0; o >>= 1) {
        cls  += __shfl_down_sync(0xFFFFFFFFu, cls,  o);
        reg  += __shfl_down_sync(0xFFFFFFFFu, reg,  o);
        npos += __shfl_down_sync(0xFFFFFFFFu, npos, o);
    }
    __shared__ float red[3][8];
    int warp = threadIdx.x >> 5, lane = threadIdx.x & 31;
    if (lane == 0) { red[0][warp] = reg; red[1][warp] = cls; red[2][warp] = npos; }
    __syncthreads();

    // ---- commit + last-block finalize (verified ticket pattern) ----
    if (threadIdx.x == 0) {
        float r0 = 0.f, r1 = 0.f, r2 = 0.f;
#pragma unroll
        for (int w = 0; w < 8; w++) { r0 += red[0][w]; r1 += red[1][w]; r2 += red[2][w]; }
        atomicAdd(&g_acc[0], (double)r0);
        atomicAdd(&g_acc[1], (double)r1);
        atomicAdd(&g_acc[2], (double)r2);
        __threadfence();
        unsigned ticket = atomicAdd(&g_done, 1u);
        if (ticket == NBLK - 1) {
            double a0 = __longlong_as_double(
                (long long)atomicExch((unsigned long long*)&g_acc[0], 0ull));
            double a1 = __longlong_as_double(
                (long long)atomicExch((unsigned long long*)&g_acc[1], 0ull));
            double a2 = __longlong_as_double(
                (long long)atomicExch((unsigned long long*)&g_acc[2], 0ull));
            atomicExch(&g_done, 0u);
            double np = (a2 < 1.0) ? 1.0 : a2;
            out[0] = (float)(a0 / (np * 4.0));
            out[1] = (float)(a1 / (np * 6.0));
        }
    }
}

extern "C" void kernel_launch(void* const* d_in, const int* in_sizes, int n_in,
                              void* d_out, int out_size) {
    const float* conf       = (const float*)d_in[0];   // (8, 60000, 150) f32
    const float* pred       = (const float*)d_in[1];   // (8, 60000, 4)   f32
    const float* gt_loc     = (const float*)d_in[2];   // (8, 60000, 4)   f32
    const int*   gt_labels  = (const int*)  d_in[3];   // (8, 20, 5, 5)   i32
    // d_in[4] = counts: not used by the computation
    const int*   labels_bin = (const int*)  d_in[5];   // (8, 60000)      i32
    float* out = (float*)d_out;

    prep_kernel<<<(BAc + 255) / 256, 256>>>(labels_bin, gt_labels);

    main_kernel<<<NBLK, 256>>>((const float4*)conf,
                               (const float4*)pred,
                               (const float4*)gt_loc,
                               out);
}

// round 17
// speedup vs baseline: 1.0320x; 1.0320x over previous
#include <cuda_runtime.h>

// ---------------------------------------------------------------------------
// Problem constants
// ---------------------------------------------------------------------------
#define Bc    8
#define Ac    60000
#define Cc    150                 // 1 + (10+19+39+69+12)
#define Gc    20
#define Tc    5
#define BAc   (Bc * Ac)           // 480,000 anchors
#define NCONF (BAc * Cc)          // 72,000,000 floats
#define NV16  (NCONF / 16)        // 4,500,000 16-channel groups
#define RW    8                   // padded words per bitmask row
#define NROWS (Bc * (Gc + 1))     // 168 rows
#define NBLK  740                 // 148 SMs * 5 blocks: single wave

#define HL2    0.34657359027997264f   // 0.5 * ln(2)

__device__ double   g_acc[3];      // [0]=reg_sum, [1]=cls_sum, [2]=num_pos
__device__ unsigned g_done;        // completed-block ticket counter

// ---------------------------------------------------------------------------
// MUFU wrappers
// ---------------------------------------------------------------------------
__device__ __forceinline__ float mufu_tanh(float x) {
    float y; asm("tanh.approx.f32 %0, %1;" : "=f"(y) : "f"(x)); return y;
}
__device__ __forceinline__ float mufu_lg2(float x) {
    float y; asm("lg2.approx.f32 %0, %1;" : "=f"(y) : "f"(x)); return y;
}

// ---------------------------------------------------------------------------
// Focal, branch/predicate-free (R15-proven):
//   sgn = label ? +0.5 : -0.5   (bit -> sign word, pure ALU)
//   t = tanh(x/2); P = 0.5 + sgn*t; w = 0.5 - sgn*t
//   coef = cp*(sgn-1), cp = mask*0.5*ln2  ->  -A*ln2*mask exactly
//   acc += coef * lg2(P) * w^2
// ---------------------------------------------------------------------------
__device__ __forceinline__ void focal(float x, unsigned nb, int k, float cp,
                                      float& acc) {
    unsigned sgnw = ((nb << (31 - k)) & 0x80000000u) | 0x3F000000u;
    float sgn  = __uint_as_float(sgnw);
    float t    = mufu_tanh(0.5f * x);
    float P    = fmaf(sgn, t, 0.5f);
    float w    = fmaf(-sgn, t, 0.5f);
    float lgP  = mufu_lg2(P);
    float coef = cp * (sgn - 1.0f);
    acc = fmaf(coef * lgP, w * w, acc);
}

// ---------------------------------------------------------------------------
// Single fused kernel: per-block bitmask build + cls/reg/npos + finalize.
//   sb row layout: bit 0 = (lb>0); bit 1+k = class-k present in group lb-1
// ---------------------------------------------------------------------------
__global__ void __launch_bounds__(256, 5)
main_kernel(const float4* __restrict__ conf4,
            const float4* __restrict__ pred4,
            const float4* __restrict__ gt4,
            const int*    __restrict__ lbin,
            const int*    __restrict__ gt_labels,
            float*        __restrict__ out) {
    // ---- per-block bitmask table (25 independent L2-hot loads/thread) ----
    __shared__ unsigned sb[NROWS * RW];        // 5.25 KB
    if (threadIdx.x < NROWS) {
        int b = threadIdx.x / (Gc + 1), g = threadIdx.x % (Gc + 1);
        unsigned w[RW] = {0u, 0u, 0u, 0u, 0u, 0u, 0u, 0u};
        if (g > 0) {
            w[0] = 1u;
            const int off[5] = {1, 11, 30, 69, 138};
            int grp = g - 1;
#pragma unroll
            for (int h = 0; h < 5; h++)
#pragma unroll
                for (int t = 0; t < Tc; t++) {
                    int v = __ldg(&gt_labels[((b * Gc + grp) * 5 + h) * Tc + t]);
                    if (v >= 0) {
                        int bit = off[h] + v;
                        w[bit >> 5] |= (1u << (bit & 31));
                    }
                }
        }
#pragma unroll
        for (int k = 0; k < RW; k++)
            sb[threadIdx.x * RW + k] = w[k];
    }
    __syncthreads();

    const int tid    = blockIdx.x * 256 + threadIdx.x;
    const int stride = NBLK * 256;

    float cls0 = 0.f, cls1 = 0.f, cls2 = 0.f, cls3 = 0.f;

    // ---- classification: 4.5M groups of 16 consecutive channels ----
    for (int j = tid; j < NV16; j += stride) {
        float4 v0 = __ldcs(&conf4[4 * j]);
        float4 v1 = __ldcs(&conf4[4 * j + 1]);
        float4 v2 = __ldcs(&conf4[4 * j + 2]);
        float4 v3 = __ldcs(&conf4[4 * j + 3]);
        unsigned base = (unsigned)j << 4;          // 16 channels per group
        unsigned a = base / (unsigned)Cc;          // magic-mul
        int c = (int)(base - a * Cc);              // even, 0..148
        int lb = __ldg(&lbin[a]);
        unsigned b = a / (unsigned)Ac;             // magic-mul
        int row = (int)(b * (Gc + 1)) + max(lb, 0);

        const unsigned* rp = &sb[(row << 3) + (c >> 5)];
        unsigned bits = __funnelshift_r(rp[0], rp[1], c);  // low 16 = labels
        float cm = (lb >= 0) ? HL2 : 0.f;          // cp = mask * 0.5*ln2
        float cp0 = cm, cp1 = cm, cp2 = cm, cp3 = cm;
        float cp4 = cm, cp5 = cm, cp6 = cm, cp7 = cm;

        if (c >= 136) {                            // anchor crossing (~9%)
            int n1c = Cc - c;                      // 2..14 lanes in anchor a
            int a2i = (int)a + 1;                  // never OOB (last c = 134)
            int lb2 = __ldg(&lbin[a2i]);
            unsigned b2 = (unsigned)a2i / (unsigned)Ac;
            int row2 = (int)(b2 * (Gc + 1)) + max(lb2, 0);
            unsigned bits2 = sb[row2 << 3];
            bits = (bits & ((1u << n1c) - 1u)) | (bits2 << n1c);
            float cm2 = (lb2 >= 0) ? HL2 : 0.f;
            if (n1c <=  2) cp1 = cm2;
            if (n1c <=  4) cp2 = cm2;
            if (n1c <=  6) cp3 = cm2;
            if (n1c <=  8) cp4 = cm2;
            if (n1c <= 10) cp5 = cm2;
            if (n1c <= 12) cp6 = cm2;
            cp7 = cm2;
        }

        unsigned nb = ~bits;

        focal(v0.x, nb,  0, cp0, cls0);
        focal(v0.y, nb,  1, cp0, cls1);
        focal(v0.z, nb,  2, cp1, cls2);
        focal(v0.w, nb,  3, cp1, cls3);
        focal(v1.x, nb,  4, cp2, cls0);
        focal(v1.y, nb,  5, cp2, cls1);
        focal(v1.z, nb,  6, cp3, cls2);
        focal(v1.w, nb,  7, cp3, cls3);
        focal(v2.x, nb,  8, cp4, cls0);
        focal(v2.y, nb,  9, cp4, cls1);
        focal(v2.z, nb, 10, cp5, cls2);
        focal(v2.w, nb, 11, cp5, cls3);
        focal(v3.x, nb, 12, cp6, cls0);
        focal(v3.y, nb, 13, cp6, cls1);
        focal(v3.z, nb, 14, cp7, cls2);
        focal(v3.w, nb, 15, cp7, cls3);
    }

    // ---- regression + pos count over 480k anchors ----
    float reg = 0.f, npos = 0.f;
    for (int a1 = tid; a1 < BAc; a1 += stride) {
        int lb = __ldg(&lbin[a1]);
        if (lb > 0) {
            npos += 1.0f;
            float4 p = pred4[a1];
            float4 g = gt4[a1];
            float d[4] = {p.x - g.x, p.y - g.y, p.z - g.z, p.w - g.w};
#pragma unroll
            for (int k = 0; k < 4; k++) {
                float n = fabsf(d[k]);
                reg += (n < (1.0f / 9.0f)) ? 4.5f * n * n : n - (1.0f / 18.0f);
            }
        }
    }

    // ---- block reduction ----
    float cls = (cls0 + cls1) + (cls2 + cls3);
#pragma unroll
    for (int o = 16; o > 0; o >>= 1) {
        cls  += __shfl_down_sync(0xFFFFFFFFu, cls,  o);
        reg  += __shfl_down_sync(0xFFFFFFFFu, reg,  o);
        npos += __shfl_down_sync(0xFFFFFFFFu, npos, o);
    }
    __shared__ float red[3][8];
    int warp = threadIdx.x >> 5, lane = threadIdx.x & 31;
    if (lane == 0) { red[0][warp] = reg; red[1][warp] = cls; red[2][warp] = npos; }
    __syncthreads();

    // ---- commit + last-block finalize (verified ticket pattern) ----
    if (threadIdx.x == 0) {
        float r0 = 0.f, r1 = 0.f, r2 = 0.f;
#pragma unroll
        for (int w = 0; w < 8; w++) { r0 += red[0][w]; r1 += red[1][w]; r2 += red[2][w]; }
        atomicAdd(&g_acc[0], (double)r0);
        atomicAdd(&g_acc[1], (double)r1);
        atomicAdd(&g_acc[2], (double)r2);
        __threadfence();
        unsigned ticket = atomicAdd(&g_done, 1u);
        if (ticket == NBLK - 1) {
            double a0 = __longlong_as_double(
                (long long)atomicExch((unsigned long long*)&g_acc[0], 0ull));
            double a1 = __longlong_as_double(
                (long long)atomicExch((unsigned long long*)&g_acc[1], 0ull));
            double a2 = __longlong_as_double(
                (long long)atomicExch((unsigned long long*)&g_acc[2], 0ull));
            atomicExch(&g_done, 0u);
            double np = (a2 < 1.0) ? 1.0 : a2;
            out[0] = (float)(a0 / (np * 4.0));
            out[1] = (float)(a1 / (np * 6.0));
        }
    }
}

extern "C" void kernel_launch(void* const* d_in, const int* in_sizes, int n_in,
                              void* d_out, int out_size) {
    const float* conf       = (const float*)d_in[0];   // (8, 60000, 150) f32
    const float* pred       = (const float*)d_in[1];   // (8, 60000, 4)   f32
    const float* gt_loc     = (const float*)d_in[2];   // (8, 60000, 4)   f32
    const int*   gt_labels  = (const int*)  d_in[3];   // (8, 20, 5, 5)   i32
    // d_in[4] = counts: not used by the computation
    const int*   labels_bin = (const int*)  d_in[5];   // (8, 60000)      i32
    float* out = (float*)d_out;

    main_kernel<<<NBLK, 256>>>((const float4*)conf,
                               (const float4*)pred,
                               (const float4*)gt_loc,
                               labels_bin, gt_labels, out);
}